// round 12
// baseline (speedup 1.0000x reference)
#include <cuda_runtime.h>
#include <cuda_bf16.h>

#define BB 256
#define TT 64
#define DD 2048
#define THRESHOLD 0.99f
#define EPSILON 0.01f
#define FULLM 0xffffffffu

// Grid: BB blocks (one per batch), 512 threads; thread owns one float4 of D.
// COMMON PATH (hs <= 3, ~96%): per-thread scalar weights from broadcast loads;
// normalization deferred to the epilogue (acc *= inv). RARE PATH (block-uniform):
// rows 4..7 prefetched before the warp-0 scan, proven round-7 structure.
__global__ void __launch_bounds__(512) act_halting_kernel(
    const float* __restrict__ halt_probs,   // [B, T]
    const float* __restrict__ outputs,      // [B, T, D]
    const float* __restrict__ step_weights, // [B, T]
    float* __restrict__ out)                // [B*D] ++ [B] ++ [B*T]
{
    const int b    = blockIdx.x;
    const int tid  = threadIdx.x;
    const int lane = tid & 31;
    const int warp = tid >> 5;

    __shared__ float swsh[TT];
    __shared__ int   s_hs;

    const float* hpb = halt_probs   + b * TT;
    const float* swb = step_weights + b * TT;

    // ---- 1) Warp 0 pre-issues full-row scan inputs (rare path never waits). ----
    float p_lo = 0.f, p_hi = 0.f, sw_lo = 0.f, sw_hi = 0.f;
    if (tid < 32) {
        p_lo  = hpb[lane];
        p_hi  = hpb[32 + lane];
        sw_lo = swb[lane];
        sw_hi = swb[32 + lane];
    }

    // ---- 2) Broadcast loads for the common path: hp[0..3], sw[0..3]. ----
    float4 hp4 = *reinterpret_cast<const float4*>(hpb);
    float4 st4 = *reinterpret_cast<const float4*>(swb);

    // ---- 3) Speculative row loads t=0..3. ----
    const float4* base = reinterpret_cast<const float4*>(outputs)
                       + (size_t)b * TT * (DD / 4) + tid;
    float4 v0 = base[0 * (DD / 4)];
    float4 v1 = base[1 * (DD / 4)];
    float4 v2 = base[2 * (DD / 4)];
    float4 v3 = base[3 * (DD / 4)];

    // ---- 4) Sequential 4-step cumsum (bitwise-matches reference order). ----
    float c0 = hp4.x;
    float c1 = c0 + hp4.y;
    float c2 = c1 + hp4.z;
    float c3 = c2 + hp4.w;

    if (c3 >= THRESHOLD) {
        // ======== COMMON PATH: hs <= 3, per-thread scalar weights. ========
        float w0 = 0.f, w1 = 0.f, w2 = 0.f, w3 = 0.f;
        if (c0 >= THRESHOLD) {
            w0 = 1.0f * st4.x;                    // hs=0: remaining = 1
        } else if (c1 >= THRESHOLD) {
            w0 = hp4.x * st4.x;                   // hs=1: remaining = 1 - c0
            w1 = (1.0f - c0) * st4.y;
        } else if (c2 >= THRESHOLD) {
            w0 = hp4.x * st4.x;                   // hs=2: remaining = 1 - c1
            w1 = hp4.y * st4.y;
            w2 = (1.0f - c1) * st4.z;
        } else {
            w0 = hp4.x * st4.x;                   // hs=3: remaining = 1 - c2
            w1 = hp4.y * st4.y;
            w2 = hp4.z * st4.z;
            w3 = (1.0f - c2) * st4.w;
        }
        float S   = ((w0 + w1) + w2) + w3;
        float inv = 1.0f / fmaxf(S, EPSILON);

        // FMAs run on UNNORMALIZED weights (starts the moment loads land);
        // single inv multiply in the epilogue.
        float4 acc;
        acc.x = (w0 * v0.x + w1 * v1.x + w2 * v2.x + w3 * v3.x) * inv;
        acc.y = (w0 * v0.y + w1 * v1.y + w2 * v2.y + w3 * v3.y) * inv;
        acc.z = (w0 * v0.z + w1 * v1.z + w2 * v2.z + w3 * v3.z) * inv;
        acc.w = (w0 * v0.w + w1 * v1.w + w2 * v2.w + w3 * v3.w) * inv;
        reinterpret_cast<float4*>(out)[(size_t)b * (DD / 4) + tid] = acc;

        // Side outputs: normalized weights as 4x float4 (lanes 0..15), zeros after.
        if (warp == 0) {
            float n0 = w0 * inv, n1 = w1 * inv, n2 = w2 * inv, n3 = w3 * inv;
            if (lane < 16) {
                float4 wv = make_float4(0.f, 0.f, 0.f, 0.f);
                if (lane == 0) wv = make_float4(n0, n1, n2, n3);
                reinterpret_cast<float4*>(out + BB * DD + BB + b * TT)[lane] = wv;
            }
            if (lane == 0)
                out[BB * DD + b] = n0 * 1.0f + n1 * 2.0f + n2 * 3.0f + n3 * 4.0f;
        }
        return;
    }

    // ======== RARE PATH (block-uniform; hs >= 4 guaranteed). ========
    // Rows 4..7 issued NOW so the second round-trip overlaps the scan.
    float4 v4 = base[4 * (DD / 4)];
    float4 v5 = base[5 * (DD / 4)];
    float4 v6 = base[6 * (DD / 4)];
    float4 v7 = base[7 * (DD / 4)];

    if (tid < 32) {
        float c_lo = p_lo, c_hi = p_hi;
        #pragma unroll
        for (int o = 1; o < 32; o <<= 1) {
            float u = __shfl_up_sync(FULLM, c_lo, o);
            float v = __shfl_up_sync(FULLM, c_hi, o);
            if (lane >= o) { c_lo += u; c_hi += v; }
        }
        float tot_lo = __shfl_sync(FULLM, c_lo, 31);
        c_hi += tot_lo;

        unsigned bl = __ballot_sync(FULLM, c_lo >= THRESHOLD);
        unsigned bh = __ballot_sync(FULLM, c_hi >= THRESHOLD);
        int hs;
        if (bl)      hs = __ffs(bl) - 1;
        else if (bh) hs = 32 + __ffs(bh) - 1;
        else         hs = TT - 1;

        const int src = hs & 31;
        float cum_lo_at = __shfl_sync(FULLM, c_lo, src);
        float cum_hi_at = __shfl_sync(FULLM, c_hi, src);
        float p_lo_at   = __shfl_sync(FULLM, p_lo, src);
        float p_hi_at   = __shfl_sync(FULLM, p_hi, src);
        float cum_at = (hs < 32) ? cum_lo_at : cum_hi_at;
        float p_at   = (hs < 32) ? p_lo_at   : p_hi_at;
        float remaining = 1.0f - cum_at + p_at;

        const int t_lo = lane, t_hi = lane + 32;
        float w0 = (t_lo < hs) ? p_lo : ((t_lo == hs) ? remaining : 0.0f);
        float w1 = (t_hi < hs) ? p_hi : ((t_hi == hs) ? remaining : 0.0f);
        w0 *= sw_lo;
        w1 *= sw_hi;

        float s = w0 + w1;
        #pragma unroll
        for (int o = 16; o; o >>= 1) s += __shfl_xor_sync(FULLM, s, o);
        float inv = 1.0f / fmaxf(s, EPSILON);
        w0 *= inv;
        w1 *= inv;

        swsh[lane]      = w0;
        swsh[lane + 32] = w1;
        if (lane == 0) s_hs = hs;

        float pd = w0 * (float)(t_lo + 1) + w1 * (float)(t_hi + 1);
        #pragma unroll
        for (int o = 16; o; o >>= 1) pd += __shfl_xor_sync(FULLM, pd, o);
        if (lane == 0) out[BB * DD + b] = pd;
        out[BB * DD + BB + b * TT + lane]      = w0;
        out[BB * DD + BB + b * TT + 32 + lane] = w1;
    }
    __syncthreads();

    const int hs = s_hs;

    float4 acc;
    {
        float w0 = swsh[0], w1 = swsh[1], w2 = swsh[2], w3 = swsh[3];
        float w4 = swsh[4], w5 = swsh[5], w6 = swsh[6], w7 = swsh[7];
        acc.x = w0 * v0.x + w1 * v1.x + w2 * v2.x + w3 * v3.x
              + w4 * v4.x + w5 * v5.x + w6 * v6.x + w7 * v7.x;
        acc.y = w0 * v0.y + w1 * v1.y + w2 * v2.y + w3 * v3.y
              + w4 * v4.y + w5 * v5.y + w6 * v6.y + w7 * v7.y;
        acc.z = w0 * v0.z + w1 * v1.z + w2 * v2.z + w3 * v3.z
              + w4 * v4.z + w5 * v5.z + w6 * v6.z + w7 * v7.z;
        acc.w = w0 * v0.w + w1 * v1.w + w2 * v2.w + w3 * v3.w
              + w4 * v4.w + w5 * v5.w + w6 * v6.w + w7 * v7.w;
    }

    // Astronomically rare (P ~ 2e-6 per batch): hs >= 8.
    for (int t = 8; t <= hs; ++t) {
        float  w = swsh[t];
        float4 v = base[(size_t)t * (DD / 4)];
        acc.x = fmaf(w, v.x, acc.x);
        acc.y = fmaf(w, v.y, acc.y);
        acc.z = fmaf(w, v.z, acc.z);
        acc.w = fmaf(w, v.w, acc.w);
    }

    reinterpret_cast<float4*>(out)[(size_t)b * (DD / 4) + tid] = acc;
}

extern "C" void kernel_launch(void* const* d_in, const int* in_sizes, int n_in,
                              void* d_out, int out_size) {
    const float* halt_probs   = (const float*)d_in[0]; // [B,T,1] = 16384
    const float* outputs      = (const float*)d_in[1]; // [B,T,D] = 33554432
    const float* step_weights = (const float*)d_in[2]; // [B,T]   = 16384
    float* out = (float*)d_out;

    act_halting_kernel<<<BB, 512>>>(halt_probs, outputs, step_weights, out);
}